// round 9
// baseline (speedup 1.0000x reference)
#include <cuda_runtime.h>
#include <cstdint>

#define B_  2
#define N_  1024
#define M_  1024
#define H_  128
#define SCALE_ (1.0f / 6.964404506368992f)  // 1 / 128^0.4

__device__ float g_es[B_ * M_];       // exp(scaled logits)
__device__ float g_psum[32 * B_];     // per-K1-block partial exp sums (32 per batch)

__device__ __forceinline__ uint32_t smem_u32(const void* p) {
    uint32_t a;
    asm("{ .reg .u64 t; cvta.to.shared.u64 t, %1; cvt.u32.u64 %0, t; }"
        : "=r"(a) : "l"(p));
    return a;
}

// ---------------------------------------------------------------------------
// K1: bulk-load W (64KB) via TMA, colsum in smem, one warp per key row,
// exp -> g_es, per-block partial sum -> g_psum.  grid 64 x 1024.
// smem layout: [0,8) mbar | [128, 65664) W | [65664, 69760) part[8][128]
//              | [69760, 70272) wcol | [70272, 70400) sh_e
// ---------------------------------------------------------------------------
#define K1_SMEM 70400
__global__ __launch_bounds__(1024) void k_exps(const float* __restrict__ keys,
                                               const float* __restrict__ W) {
    extern __shared__ char smem[];
    float* shW  = reinterpret_cast<float*>(smem + 128);
    float* part = reinterpret_cast<float*>(smem + 65664);
    float* wcol = reinterpret_cast<float*>(smem + 69760);
    float* sh_e = reinterpret_cast<float*>(smem + 70272);

    const int tid  = threadIdx.x;
    const int lane = tid & 31;
    const int warp = tid >> 5;
    const int blk  = blockIdx.x;
    const uint32_t mbar = smem_u32(smem);

    if (tid == 0) {
        asm volatile("mbarrier.init.shared.b64 [%0], 1;" :: "r"(mbar) : "memory");
    }
    __syncthreads();
    if (tid == 0) {
        asm volatile("mbarrier.arrive.expect_tx.shared.b64 _, [%0], %1;"
                     :: "r"(mbar), "r"(65536u) : "memory");
        asm volatile(
            "cp.async.bulk.shared::cta.global.mbarrier::complete_tx::bytes "
            "[%0], [%1], %2, [%3];"
            :: "r"(smem_u32(shW)), "l"(W), "r"(65536u), "r"(mbar) : "memory");
    }

    // keys row for this warp -> registers (overlaps with the bulk copy)
    const int row = blk * 32 + warp;                     // [0, 2048)
    const float4 k4 = reinterpret_cast<const float4*>(keys)[row * 32 + lane];

    // wait for W
    {
        uint32_t done;
        asm volatile(
            "{\n\t.reg .pred p;\n\t"
            "mbarrier.try_wait.parity.acquire.cta.shared::cta.b64 p, [%1], 0;\n\t"
            "selp.b32 %0, 1, 0, p;\n\t}"
            : "=r"(done) : "r"(mbar) : "memory");
        while (!done) {
            asm volatile(
                "{\n\t.reg .pred p;\n\t"
                "mbarrier.try_wait.parity.acquire.cta.shared::cta.b64 p, [%1], 0, 0x989680;\n\t"
                "selp.b32 %0, 1, 0, p;\n\t}"
                : "=r"(done) : "r"(mbar) : "memory");
        }
    }
    __syncthreads();

    // colsum: thread (g = tid>>7, c = tid&127) sums 16 rows of column c
    {
        const int c = tid & (H_ - 1);
        const int g = tid >> 7;
        float a0 = 0.f, a1 = 0.f, a2 = 0.f, a3 = 0.f;
        #pragma unroll
        for (int r = 0; r < 16; r += 4) {
            a0 += shW[(g * 16 + r + 0) * H_ + c];
            a1 += shW[(g * 16 + r + 1) * H_ + c];
            a2 += shW[(g * 16 + r + 2) * H_ + c];
            a3 += shW[(g * 16 + r + 3) * H_ + c];
        }
        part[g * H_ + c] = (a0 + a1) + (a2 + a3);
    }
    __syncthreads();
    if (tid < H_) {
        float w = 0.f;
        #pragma unroll
        for (int g = 0; g < 8; ++g) w += part[g * H_ + tid];
        wcol[tid] = w;
    }
    __syncthreads();

    // dot + exp
    const float4 w4 = reinterpret_cast<const float4*>(wcol)[lane];
    float acc = k4.x * w4.x + k4.y * w4.y + k4.z * w4.z + k4.w * w4.w;
    #pragma unroll
    for (int o = 16; o > 0; o >>= 1) acc += __shfl_xor_sync(0xffffffffu, acc, o);
    if (lane == 0) {
        const float e = __expf(SCALE_ * acc);
        __stcg(&g_es[row], e);
        sh_e[warp] = e;
    }
    __syncthreads();
    if (warp == 0) {
        float v = sh_e[lane];
        #pragma unroll
        for (int o = 16; o > 0; o >>= 1) v += __shfl_xor_sync(0xffffffffu, v, o);
        if (lane == 0) __stcg(&g_psum[blk], v);   // blk 0..31 batch0, 32..63 batch1
    }
}

// ---------------------------------------------------------------------------
// K2: denom reduce + scale + stage 16 output rows (64 KB) + one bulk store.
// grid 128 x 1024; block b handles output rows [b*16, b*16+16).
// ---------------------------------------------------------------------------
#define K2_SMEM (65536 + 4096 + 64 + 16)
__global__ __launch_bounds__(1024) void k_out(const float* __restrict__ values,
                                              float* __restrict__ out) {
    extern __shared__ char smem[];
    float4* buf    = reinterpret_cast<float4*>(smem);
    float*  sh_s   = reinterpret_cast<float*>(smem + 65536);
    float*  sh_val = reinterpret_cast<float*>(smem + 65536 + 4096);
    float*  sh_inv = reinterpret_cast<float*>(smem + 65536 + 4096 + 64);

    const int tid = threadIdx.x;
    const int lane = tid & 31;
    const int warp = tid >> 5;
    const int blk = blockIdx.x;
    const int b = blk >> 6;                              // 64 blocks per batch

    const float e = __ldcg(&g_es[b * M_ + tid]);
    if (warp == 0) {
        float p = __ldcg(&g_psum[b * 32 + lane]);
        #pragma unroll
        for (int o = 16; o > 0; o >>= 1) p += __shfl_xor_sync(0xffffffffu, p, o);
        if (lane == 0) *sh_inv = 1.0f / p;
    }
    if (warp == 1 && lane < 16) sh_val[lane] = values[blk * 16 + lane];
    __syncthreads();

    sh_s[tid] = e * (*sh_inv);
    __syncthreads();

    const int r0 = tid >> 8;                             // 0..3
    const int col = tid & 255;
    const float4 s4 = reinterpret_cast<const float4*>(sh_s)[col];
    #pragma unroll
    for (int i = 0; i < 4; ++i) {
        const int rl = i * 4 + r0;                       // local row 0..15
        const float v = sh_val[rl];
        buf[rl * 256 + col] = make_float4(s4.x * v, s4.y * v, s4.z * v, s4.w * v);
    }
    __syncthreads();
    if (tid == 0) {
        asm volatile("fence.proxy.async;" ::: "memory");
        const float* gdst = out + (size_t)blk * 16 * M_;
        asm volatile("cp.async.bulk.global.shared::cta.bulk_group [%0], [%1], %2;"
                     :: "l"(gdst), "r"(smem_u32(buf)), "r"(65536) : "memory");
        asm volatile("cp.async.bulk.commit_group;" ::: "memory");
        asm volatile("cp.async.bulk.wait_group 0;" ::: "memory");
    }
}

extern "C" void kernel_launch(void* const* d_in, const int* in_sizes, int n_in,
                              void* d_out, int out_size) {
    // metadata order: queries, keys, values, W, b (queries & bias cancel in softmax)
    const float* keys   = (const float*)d_in[1];
    const float* values = (const float*)d_in[2];
    const float* W      = (const float*)d_in[3];
    float* out = (float*)d_out;

    cudaFuncSetAttribute(k_exps, cudaFuncAttributeMaxDynamicSharedMemorySize,
                         K1_SMEM);
    cudaFuncSetAttribute(k_out, cudaFuncAttributeMaxDynamicSharedMemorySize,
                         K2_SMEM);

    k_exps<<<64, 1024, K1_SMEM>>>(keys, W);
    k_out<<<128, 1024, K2_SMEM>>>(values, out);
}

// round 12
// speedup vs baseline: 1.0208x; 1.0208x over previous
#include <cuda_runtime.h>
#include <cstdint>

#define B_  2
#define N_  1024
#define M_  1024
#define H_  128
#define G_  128
#define SCALE_ (1.0f / 6.964404506368992f)  // 1 / 128^0.4

__device__ float g_es[B_ * M_];       // exp(scaled logits)
__device__ float g_psum[G_];          // per-block partial exp sums (64 per batch)
__device__ unsigned g_count;          // monotonic ticket barrier (zero-init)

// dyn smem layout (bytes):
//   [0,8)           mbar
//   [128, 65664)    W tile (64 KB)
//   [65664, 82048)  part[1024] float4 partial colsums (16 KB)
//   [82048, 82560)  wcol[128]
//   [82560, 82624)  sh_e[16]
//   [82624, 86720)  sh_s[1024]
//   [86720, 86724)  sh_inv
#define SMEM_BYTES 86784

__device__ __forceinline__ uint32_t smem_u32(const void* p) {
    uint32_t a;
    asm("{ .reg .u64 t; cvta.to.shared.u64 t, %1; cvt.u32.u64 %0, t; }"
        : "=r"(a) : "l"(p));
    return a;
}

__global__ __launch_bounds__(1024) void k_fused(const float* __restrict__ keys,
                                                const float* __restrict__ values,
                                                const float* __restrict__ W,
                                                float* __restrict__ out) {
    extern __shared__ char smem[];
    float*  shW    = reinterpret_cast<float*>(smem + 128);
    float4* part   = reinterpret_cast<float4*>(smem + 65664);   // 1024 float4
    float*  wcol   = reinterpret_cast<float*>(smem + 82048);
    float*  sh_e   = reinterpret_cast<float*>(smem + 82560);
    float*  sh_s   = reinterpret_cast<float*>(smem + 82624);
    float*  sh_inv = reinterpret_cast<float*>(smem + 86720);

    const int tid  = threadIdx.x;
    const int lane = tid & 31;
    const int warp = tid >> 5;
    const int blk  = blockIdx.x;
    const uint32_t mbar = smem_u32(smem);

    // ---------------- Phase A: init mbar, sync, THEN issue bulk W copy -----
    if (tid == 0) {
        asm volatile("mbarrier.init.shared.b64 [%0], 1;" :: "r"(mbar) : "memory");
    }
    __syncthreads();
    if (tid == 0) {
        asm volatile("mbarrier.arrive.expect_tx.shared.b64 _, [%0], %1;"
                     :: "r"(mbar), "r"(65536u) : "memory");
        asm volatile(
            "cp.async.bulk.shared::cta.global.mbarrier::complete_tx::bytes "
            "[%0], [%1], %2, [%3];"
            :: "r"(smem_u32(shW)), "l"(W), "r"(65536u), "r"(mbar) : "memory");
    }

    // keys rows for this block (16 rows, one warp each) -> registers
    float4 k4 = make_float4(0.f, 0.f, 0.f, 0.f);
    if (warp < 16)
        k4 = reinterpret_cast<const float4*>(keys)[(blk * 16 + warp) * 32 + lane];

    // ---------------- wait for W ------------------------------------------
    {
        uint32_t done;
        asm volatile(
            "{\n\t.reg .pred p;\n\t"
            "mbarrier.try_wait.parity.acquire.cta.shared::cta.b64 p, [%1], 0;\n\t"
            "selp.b32 %0, 1, 0, p;\n\t}"
            : "=r"(done) : "r"(mbar) : "memory");
        while (!done) {
            asm volatile(
                "{\n\t.reg .pred p;\n\t"
                "mbarrier.try_wait.parity.acquire.cta.shared::cta.b64 p, [%1], 0, 0x989680;\n\t"
                "selp.b32 %0, 1, 0, p;\n\t}"
                : "=r"(done) : "r"(mbar) : "memory");
        }
    }
    __syncthreads();

    // ---------------- Phase B: colsum(W) in smem ---------------------------
    {
        const int c4 = tid & 31;              // float4 column
        const int g  = tid >> 5;              // 32 groups x 4 rows
        const float4* W4 = reinterpret_cast<const float4*>(shW);
        float4 a = W4[(g * 4 + 0) * 32 + c4];
        float4 b1 = W4[(g * 4 + 1) * 32 + c4];
        float4 c1 = W4[(g * 4 + 2) * 32 + c4];
        float4 d1 = W4[(g * 4 + 3) * 32 + c4];
        part[g * 32 + c4] = make_float4((a.x + b1.x) + (c1.x + d1.x),
                                        (a.y + b1.y) + (c1.y + d1.y),
                                        (a.z + b1.z) + (c1.z + d1.z),
                                        (a.w + b1.w) + (c1.w + d1.w));
    }
    __syncthreads();
    if (tid < 32) {
        float4 s = make_float4(0.f, 0.f, 0.f, 0.f);
        #pragma unroll
        for (int g = 0; g < 32; ++g) {
            float4 p = part[g * 32 + tid];
            s.x += p.x; s.y += p.y; s.z += p.z; s.w += p.w;
        }
        reinterpret_cast<float4*>(wcol)[tid] = s;
    }
    __syncthreads();

    // ---------------- dots + exp + block partial sum -----------------------
    if (warp < 16) {
        const float4 w4 = reinterpret_cast<const float4*>(wcol)[lane];
        float acc = k4.x * w4.x + k4.y * w4.y + k4.z * w4.z + k4.w * w4.w;
        #pragma unroll
        for (int o = 16; o > 0; o >>= 1) acc += __shfl_xor_sync(0xffffffffu, acc, o);
        if (lane == 0) {
            const float e = __expf(SCALE_ * acc);
            __stcg(&g_es[blk * 16 + warp], e);
            sh_e[warp] = e;
        }
    }
    __syncthreads();
    if (warp == 0) {
        float v = (lane < 16) ? sh_e[lane] : 0.f;
        #pragma unroll
        for (int o = 16; o > 0; o >>= 1) v += __shfl_xor_sync(0xffffffffu, v, o);
        if (lane == 0) __stcg(&g_psum[blk], v);   // blocks 0..63 batch0, 64..127 batch1
    }

    // ---------------- grid barrier (monotonic ticket) ----------------------
    __syncthreads();
    if (tid == 0) {
        __threadfence();
        const unsigned ticket = atomicAdd(&g_count, 1u);
        const unsigned target = (ticket / G_ + 1u) * G_;
        while (*((volatile unsigned*)&g_count) < target) { }
        __threadfence();
    }
    __syncthreads();

    // ---------------- Phase C: denom + softmax row -------------------------
    const int b = blk >> 6;
    const float e = __ldcg(&g_es[b * M_ + tid]);
    if (warp == 0) {
        float p = __ldcg(&g_psum[b * 64 + lane]) + __ldcg(&g_psum[b * 64 + 32 + lane]);
        #pragma unroll
        for (int o = 16; o > 0; o >>= 1) p += __shfl_xor_sync(0xffffffffu, p, o);
        if (lane == 0) *sh_inv = 1.0f / p;
    }
    __syncthreads();
    sh_s[tid] = e * (*sh_inv);
    __syncthreads();

    // ---------------- Phase D: write 16 output rows (STG.128) --------------
    const int r0  = tid >> 8;                  // 0..3
    const int col = tid & 255;
    const float4 s4 = reinterpret_cast<const float4*>(sh_s)[col];
    float4* o4 = reinterpret_cast<float4*>(out);
    #pragma unroll
    for (int i = 0; i < 4; ++i) {
        const int row = blk * 16 + i * 4 + r0;
        const float v = __ldg(values + row);
        o4[(size_t)row * 256 + col] =
            make_float4(s4.x * v, s4.y * v, s4.z * v, s4.w * v);
    }
}

extern "C" void kernel_launch(void* const* d_in, const int* in_sizes, int n_in,
                              void* d_out, int out_size) {
    // metadata order: queries, keys, values, W, b (queries & bias cancel in softmax)
    const float* keys   = (const float*)d_in[1];
    const float* values = (const float*)d_in[2];
    const float* W      = (const float*)d_in[3];
    float* out = (float*)d_out;

    cudaFuncSetAttribute(k_fused, cudaFuncAttributeMaxDynamicSharedMemorySize,
                         SMEM_BYTES);
    k_fused<<<G_, 1024, SMEM_BYTES>>>(keys, values, W, out);
}